// round 14
// baseline (speedup 1.0000x reference)
// v14: side chain 5->3 launches: k_zero folded into k_node (hist restore),
// scan_b folded into scan_a (last-block pattern). k_proj/k_node unchanged from v13.
#include <cuda_runtime.h>
#include <cuda_fp16.h>
#include <math.h>

#define NN 50000
#define NE 800000
#define DD 64
#define NBLK 196   // ceil(50000/256)

typedef unsigned long long ull;

// ---------------- packed f32x2 helpers (Blackwell FFMA2; PTX-only) ----------------
__device__ __forceinline__ ull pk2(float x, float y) {
    ull r; asm("mov.b64 %0, {%1,%2};" : "=l"(r) : "f"(x), "f"(y)); return r;
}
__device__ __forceinline__ float2 unpk2(ull v) {
    float2 r; asm("mov.b64 {%0,%1}, %2;" : "=f"(r.x), "=f"(r.y) : "l"(v)); return r;
}
__device__ __forceinline__ void fma2(ull& d, ull a, ull b) {
    asm("fma.rn.f32x2 %0, %1, %2, %0;" : "+l"(d) : "l"(a), "l"(b));
}

// ---------------- scratch (static device globals; no allocation) ----------------
// Interleaved per-node record: 256B = lane gl's uint4 = {Ps[4gl..4gl+3], nf[4gl..4gl+3]} halves.
__device__ __half2 g_PsNf[NN * 64];
__device__ __half2 g_Pdh[NN * 32];    // fp16: nf @ W_attn[64:128]
__device__ float   g_Ob[NN * DD];     // fp32: nf @ W_node[0:64] + b_node
__device__ int     g_esrc[NE];        // src ids sorted by dst (dense CSR payload)
__device__ int     g_rank[NE];        // rank of edge within its dst group
__device__ int     g_hist[NN];        // in-degree; ZEROED by k_node after use (BSS-zero call 1)
__device__ int     g_off[NN];         // block-local exclusive prefix of hist
__device__ int     g_bsum[256];
__device__ int     g_bpre[256];       // exclusive prefix of block sums
__device__ int     g_done;            // last-block counter for fused scan (reset each call)

// ---------------- kernels ----------------

// In-degree histogram (dst only) + per-edge rank (atomic return value).
__global__ __launch_bounds__(256) void k_hist(const int* __restrict__ dst) {
    int i = blockIdx.x * blockDim.x + threadIdx.x;   // NE/4 threads
    if (i < NE / 4) {
        int4 d = ((const int4*)dst)[i];
        int4 r;
        r.x = atomicAdd(&g_hist[d.x], 1);
        r.y = atomicAdd(&g_hist[d.y], 1);
        r.z = atomicAdd(&g_hist[d.z], 1);
        r.w = atomicAdd(&g_hist[d.w], 1);
        ((int4*)g_rank)[i] = r;
    }
}

// Fused hierarchical scan: per-block exclusive scan + last-block scans the block sums.
__global__ __launch_bounds__(256) void k_scan_ab() {
    int i = blockIdx.x * 256 + threadIdx.x;
    int v = (i < NN) ? g_hist[i] : 0;
    int lane = threadIdx.x & 31;
    int w    = threadIdx.x >> 5;

    int x = v;
#pragma unroll
    for (int o = 1; o < 32; o <<= 1) {
        int t = __shfl_up_sync(0xffffffffu, x, o);
        if (lane >= o) x += t;
    }
    __shared__ int ws[8];
    if (lane == 31) ws[w] = x;
    __syncthreads();
    if (w == 0 && lane < 8) {
        int y = ws[lane];
#pragma unroll
        for (int o = 1; o < 8; o <<= 1) {
            int t = __shfl_up_sync(0xffu, y, o);
            if (lane >= o) y += t;
        }
        ws[lane] = y;
    }
    __syncthreads();
    int incl = x + (w ? ws[w - 1] : 0);
    if (i < NN) g_off[i] = incl - v;               // block-local exclusive
    if (threadIdx.x == 255) g_bsum[blockIdx.x] = incl;

    // --- last-block: scan the 196 block sums into g_bpre ---
    __threadfence();
    __shared__ int sLast;
    if (threadIdx.x == 0) sLast = (atomicAdd(&g_done, 1) == (int)gridDim.x - 1);
    __syncthreads();
    if (sLast) {
        int t = threadIdx.x;
        int bv = (t < NBLK) ? g_bsum[t] : 0;
        int bx = bv;
#pragma unroll
        for (int o = 1; o < 32; o <<= 1) {
            int s = __shfl_up_sync(0xffffffffu, bx, o);
            if (lane >= o) bx += s;
        }
        __shared__ int ws2[8];
        if (lane == 31) ws2[w] = bx;
        __syncthreads();
        if (w == 0 && lane < 8) {
            int y = ws2[lane];
#pragma unroll
            for (int o = 1; o < 8; o <<= 1) {
                int s = __shfl_up_sync(0xffu, y, o);
                if (lane >= o) y += s;
            }
            ws2[lane] = y;
        }
        __syncthreads();
        int bincl = bx + (w ? ws2[w - 1] : 0);
        g_bpre[t] = bincl - bv;                     // exclusive block prefix
        if (t == 0) g_done = 0;                     // reset for next call
    }
}

// Scatter src ids into dst-sorted CSR order. Slot = local off + block prefix + rank.
__global__ __launch_bounds__(256) void k_scatter(
    const int* __restrict__ src, const int* __restrict__ dst)
{
    int e = blockIdx.x * blockDim.x + threadIdx.x;
    if (e < NE) {
        int d = __ldg(dst + e);
        int slot = __ldg(&g_off[d]) + __ldg(&g_bpre[d >> 8]) + __ldg(&g_rank[e]);
        g_esrc[slot] = __ldg(src + e);
    }
}

// Per-node projections via packed FFMA2. Warp per 4 nodes, grid-stride (592 blocks).
__global__ __launch_bounds__(256) void k_proj(
    const float* __restrict__ nf, const float* __restrict__ Wa,
    const float* __restrict__ Wn, const float* __restrict__ bn)
{
    __shared__ float sWa[4096];  // W_attn top   [64,64]
    __shared__ float sWb[4096];  // W_attn bottom[64,64]
    __shared__ float sWn[4096];  // W_node top   [64,64]
    for (int i = threadIdx.x; i < 4096; i += blockDim.x) {
        sWa[i] = Wa[i];
        sWb[i] = Wa[4096 + i];
        sWn[i] = Wn[i];
    }
    __syncthreads();

    const int lane   = threadIdx.x & 31;
    const int warp   = (blockIdx.x * blockDim.x + threadIdx.x) >> 5;
    const int nwarps = (gridDim.x * blockDim.x) >> 5;

    const float2* nf2 = (const float2*)nf;
    const double* dWa = (const double*)sWa;
    const double* dWb = (const double*)sWb;
    const double* dWn = (const double*)sWn;
    float2*       Ob2 = (float2*)g_Ob;

    float2 bb = ((const float2*)bn)[lane];

    const int psSlot = ((lane >> 1) << 2) + (lane & 1);
    const int nfSlot = psSlot + 2;

    for (int n0 = warp * 4; n0 < NN; n0 += nwarps * 4) {
        float2 xv[4];
#pragma unroll
        for (int j = 0; j < 4; j++) xv[j] = nf2[(n0 + j) * 32 + lane];

        ull aS[4], aD[4], aN[4];
#pragma unroll
        for (int j = 0; j < 4; j++) { aS[j] = 0ull; aD[j] = 0ull; aN[j] = 0ull; }

#pragma unroll 8
        for (int k = 0; k < 64; k++) {
            ull wa = __double_as_longlong(dWa[k * 32 + lane]);
            ull wb = __double_as_longlong(dWb[k * 32 + lane]);
            ull wn = __double_as_longlong(dWn[k * 32 + lane]);
#pragma unroll
            for (int j = 0; j < 4; j++) {
                float xk = __shfl_sync(0xffffffffu, (k & 1) ? xv[j].y : xv[j].x, k >> 1);
                ull xkk = pk2(xk, xk);
                fma2(aS[j], xkk, wa);
                fma2(aD[j], xkk, wb);
                fma2(aN[j], xkk, wn);
            }
        }
#pragma unroll
        for (int j = 0; j < 4; j++) {
            int n = n0 + j;
            float2 s = unpk2(aS[j]);
            float2 d = unpk2(aD[j]);
            float2 o = unpk2(aN[j]);
            g_PsNf[n * 64 + psSlot] = __floats2half2_rn(s.x, s.y);
            g_PsNf[n * 64 + nfSlot] = __floats2half2_rn(xv[j].x, xv[j].y);
            g_Pdh [n * 32 + lane]   = __floats2half2_rn(d.x, d.y);
            o.x += bb.x; o.y += bb.y;
            Ob2[n * 32 + lane] = o;
        }
    }
}

// FUSED edge+node kernel. Half-warp (16 lanes) per dst-node, grid-stride (592 blocks).
// Zeroes g_hist[v] after reading deg (restores invariant; replaces k_zero kernel).
__global__ __launch_bounds__(256) void k_node(
    const float* __restrict__ ba, const float* __restrict__ wfc,
    const float* __restrict__ Wn, float* __restrict__ out)
{
    __shared__ float sW[4096];  // W_node bottom [64,64]
    for (int i = threadIdx.x; i < 4096; i += blockDim.x)
        sW[i] = Wn[4096 + i];
    __syncthreads();

    const int lane   = threadIdx.x & 31;
    const int gl     = lane & 15;
    const int grp    = lane >> 4;
    const int gbase  = lane & 16;
    const unsigned gmask = 0xFFFFu << gbase;
    const int warp   = (blockIdx.x * blockDim.x + threadIdx.x) >> 5;
    const int nwarps = (gridDim.x * blockDim.x) >> 5;

    float4 b = ((const float4*)ba)[gl];
    float4 w = ((const float4*)wfc)[gl];
    const __half2 w01h = __floats2half2_rn(w.x, w.y);
    const __half2 w23h = __floats2half2_rn(w.z, w.w);
    const __half2 hzero = __floats2half2_rn(0.f, 0.f);

    const uint4*  PsNf = (const uint4*)g_PsNf;
    const uint2*  Pd   = (const uint2*)g_Pdh;
    const float4* sW4  = (const float4*)sW;
    const float4* Ob4  = (const float4*)g_Ob;
    float4*       out4 = (float4*)out;

    for (int v = warp * 2 + grp; v < NN; v += nwarps * 2) {
        int beg = __ldg(&g_off[v]) + __ldg(&g_bpre[v >> 8]);
        int deg = __ldg(&g_hist[v]);
        if (gl == 0) g_hist[v] = 0;        // restore invariant for next call
        int end = beg + deg;

        float4 o = Ob4[v * 16 + gl];

        if (deg > 0) {
            uint2 pdu = __ldg(&Pd[v * 16 + gl]);
            float2 pd0 = __half22float2(*(const __half2*)&pdu.x);
            float2 pd1 = __half22float2(*(const __half2*)&pdu.y);
            const __half2 pdb01 = __floats2half2_rn(pd0.x + b.x, pd0.y + b.y);
            const __half2 pdb23 = __floats2half2_rn(pd1.x + b.z, pd1.y + b.w);

            float4 acc = make_float4(0.f, 0.f, 0.f, 0.f);
            float ssum = 0.f;

#pragma unroll 4
            for (int i = beg; i < end; i++) {
                int s = __ldg(&g_esrc[i]);
                uint4 r = __ldg(&PsNf[s * 16 + gl]);

                __half2 h01 = __hmax2(__hadd2(*(const __half2*)&r.x, pdb01), hzero);
                __half2 h23 = __hmax2(__hadd2(*(const __half2*)&r.y, pdb23), hzero);
                __half2 ph  = __hfma2(h23, w23h, __hmul2(h01, w01h));
                float2 pf = __half22float2(ph);
                float p = pf.x + pf.y;

                p += __shfl_xor_sync(gmask, p, 8);
                p += __shfl_xor_sync(gmask, p, 4);
                p += __shfl_xor_sync(gmask, p, 2);
                p += __shfl_xor_sync(gmask, p, 1);

                float lg = fmaxf(p, 0.01f * p);
                float ev = __expf(lg);

                float2 x0 = __half22float2(*(const __half2*)&r.z);
                float2 x1 = __half22float2(*(const __half2*)&r.w);
                acc.x = fmaf(ev, x0.x, acc.x);
                acc.y = fmaf(ev, x0.y, acc.y);
                acc.z = fmaf(ev, x1.x, acc.z);
                acc.w = fmaf(ev, x1.y, acc.w);
                ssum += ev;
            }

            float inv = 1.f / (ssum * (float)deg);
            float a[4] = { acc.x * inv, acc.y * inv, acc.z * inv, acc.w * inv };

#pragma unroll
            for (int k = 0; k < 64; k++) {
                float ak = __shfl_sync(gmask, a[k & 3], gbase + (k >> 2));
                float4 wv = sW4[k * 16 + gl];
                o.x = fmaf(ak, wv.x, o.x);
                o.y = fmaf(ak, wv.y, o.y);
                o.z = fmaf(ak, wv.z, o.z);
                o.w = fmaf(ak, wv.w, o.w);
            }
        }
        out4[v * 16 + gl] = o;
    }
}

// ---------------- launch: fork-join of independent pipelines ----------------
namespace {
struct SideStream {
    cudaStream_t s;
    cudaEvent_t  fork, join;
    SideStream() {
        cudaStreamCreateWithFlags(&s, cudaStreamNonBlocking);
        cudaEventCreateWithFlags(&fork, cudaEventDisableTiming);
        cudaEventCreateWithFlags(&join, cudaEventDisableTiming);
    }
};
SideStream g_ss;  // constructed at load; no per-call conditionals
}

extern "C" void kernel_launch(void* const* d_in, const int* in_sizes, int n_in,
                              void* d_out, int out_size)
{
    const float* nf   = (const float*)d_in[0];
    const int*   src  = (const int*)d_in[1];
    const int*   dst  = (const int*)d_in[2];
    const float* Wa   = (const float*)d_in[3];
    const float* ba   = (const float*)d_in[4];
    const float* wfc  = (const float*)d_in[5];
    const float* Wn   = (const float*)d_in[6];
    const float* bn   = (const float*)d_in[7];
    float*       out  = (float*)d_out;

    (void)in_sizes; (void)n_in; (void)out_size;

    // fork: side stream runs the graph-structure pipeline (ints only, 3 kernels)
    cudaEventRecord(g_ss.fork, 0);
    cudaStreamWaitEvent(g_ss.s, g_ss.fork, 0);

    k_hist<<<(NE / 4 + 255) / 256, 256, 0, g_ss.s>>>(dst);
    k_scan_ab<<<NBLK, 256, 0, g_ss.s>>>();
    k_scatter<<<(NE + 255) / 256, 256, 0, g_ss.s>>>(src, dst);
    cudaEventRecord(g_ss.join, g_ss.s);

    // main stream: feature projections (floats only), concurrent with above
    k_proj<<<592, 256>>>(nf, Wa, Wn, bn);

    // join, then fused edge+node kernel
    cudaStreamWaitEvent(0, g_ss.join, 0);
    k_node<<<592, 256>>>(ba, wfc, Wn, out);
}

// round 16
// speedup vs baseline: 1.2269x; 1.2269x over previous
// v16: v15 minus the unsupported redux.f32 (reverted to proven group-mask shfl tree).
// Keeps: k_proj 8 nodes/warp, k_hist 8 edges/thread, v13 launch structure.
#include <cuda_runtime.h>
#include <cuda_fp16.h>
#include <math.h>

#define NN 50000
#define NE 800000
#define DD 64
#define NBLK 196   // ceil(50000/256)

typedef unsigned long long ull;

// ---------------- packed f32x2 helpers (Blackwell FFMA2; PTX-only) ----------------
__device__ __forceinline__ ull pk2(float x, float y) {
    ull r; asm("mov.b64 %0, {%1,%2};" : "=l"(r) : "f"(x), "f"(y)); return r;
}
__device__ __forceinline__ float2 unpk2(ull v) {
    float2 r; asm("mov.b64 {%0,%1}, %2;" : "=f"(r.x), "=f"(r.y) : "l"(v)); return r;
}
__device__ __forceinline__ void fma2(ull& d, ull a, ull b) {
    asm("fma.rn.f32x2 %0, %1, %2, %0;" : "+l"(d) : "l"(a), "l"(b));
}

// ---------------- scratch (static device globals; no allocation) ----------------
// Interleaved per-node record: 256B = lane gl's uint4 = {Ps[4gl..4gl+3], nf[4gl..4gl+3]} halves.
__device__ __half2 g_PsNf[NN * 64];
__device__ __half2 g_Pdh[NN * 32];    // fp16: nf @ W_attn[64:128]
__device__ float   g_Ob[NN * DD];     // fp32: nf @ W_node[0:64] + b_node
__device__ int     g_esrc[NE];        // src ids sorted by dst (dense CSR payload)
__device__ int     g_rank[NE];        // rank of edge within its dst group
__device__ int     g_hist[NN];        // in-degree histogram
__device__ int     g_off[NN];         // block-local exclusive prefix of hist
__device__ int     g_bsum[256];
__device__ int     g_bpre[256];       // exclusive prefix of block sums

// ---------------- kernels ----------------

__global__ void k_zero_hist() {
    int i = blockIdx.x * blockDim.x + threadIdx.x;
    if (i < NN) g_hist[i] = 0;
}

// In-degree histogram (dst only) + per-edge rank. 8 edges/thread for MLP.
__global__ __launch_bounds__(256) void k_hist(const int* __restrict__ dst) {
    int i = blockIdx.x * blockDim.x + threadIdx.x;   // NE/8 threads
    if (i < NE / 8) {
        int4 d0 = ((const int4*)dst)[i * 2];
        int4 d1 = ((const int4*)dst)[i * 2 + 1];
        int4 r0, r1;
        r0.x = atomicAdd(&g_hist[d0.x], 1);
        r0.y = atomicAdd(&g_hist[d0.y], 1);
        r0.z = atomicAdd(&g_hist[d0.z], 1);
        r0.w = atomicAdd(&g_hist[d0.w], 1);
        r1.x = atomicAdd(&g_hist[d1.x], 1);
        r1.y = atomicAdd(&g_hist[d1.y], 1);
        r1.z = atomicAdd(&g_hist[d1.z], 1);
        r1.w = atomicAdd(&g_hist[d1.w], 1);
        ((int4*)g_rank)[i * 2]     = r0;
        ((int4*)g_rank)[i * 2 + 1] = r1;
    }
}

// Per-node projections via packed FFMA2. Warp per 8 nodes (amortize weight LDS 2x).
__global__ __launch_bounds__(256) void k_proj(
    const float* __restrict__ nf, const float* __restrict__ Wa,
    const float* __restrict__ Wn, const float* __restrict__ bn)
{
    __shared__ float sWa[4096];  // W_attn top   [64,64]
    __shared__ float sWb[4096];  // W_attn bottom[64,64]
    __shared__ float sWn[4096];  // W_node top   [64,64]
    for (int i = threadIdx.x; i < 4096; i += blockDim.x) {
        sWa[i] = Wa[i];
        sWb[i] = Wa[4096 + i];
        sWn[i] = Wn[i];
    }
    __syncthreads();

    const int lane   = threadIdx.x & 31;
    const int warp   = (blockIdx.x * blockDim.x + threadIdx.x) >> 5;
    const int nwarps = (gridDim.x * blockDim.x) >> 5;

    const float2* nf2 = (const float2*)nf;
    const double* dWa = (const double*)sWa;
    const double* dWb = (const double*)sWb;
    const double* dWn = (const double*)sWn;
    float2*       Ob2 = (float2*)g_Ob;

    float2 bb = ((const float2*)bn)[lane];

    const int psSlot = ((lane >> 1) << 2) + (lane & 1);
    const int nfSlot = psSlot + 2;

    // 50000 % 8 == 0, groups always full.
    for (int n0 = warp * 8; n0 < NN; n0 += nwarps * 8) {
        float2 xv[8];
#pragma unroll
        for (int j = 0; j < 8; j++) xv[j] = nf2[(n0 + j) * 32 + lane];

        ull aS[8], aD[8], aN[8];
#pragma unroll
        for (int j = 0; j < 8; j++) { aS[j] = 0ull; aD[j] = 0ull; aN[j] = 0ull; }

#pragma unroll 4
        for (int k = 0; k < 64; k++) {
            ull wa = __double_as_longlong(dWa[k * 32 + lane]);
            ull wb = __double_as_longlong(dWb[k * 32 + lane]);
            ull wn = __double_as_longlong(dWn[k * 32 + lane]);
#pragma unroll
            for (int j = 0; j < 8; j++) {
                float xk = __shfl_sync(0xffffffffu, (k & 1) ? xv[j].y : xv[j].x, k >> 1);
                ull xkk = pk2(xk, xk);
                fma2(aS[j], xkk, wa);
                fma2(aD[j], xkk, wb);
                fma2(aN[j], xkk, wn);
            }
        }
#pragma unroll
        for (int j = 0; j < 8; j++) {
            int n = n0 + j;
            float2 s = unpk2(aS[j]);
            float2 d = unpk2(aD[j]);
            float2 o = unpk2(aN[j]);
            g_PsNf[n * 64 + psSlot] = __floats2half2_rn(s.x, s.y);
            g_PsNf[n * 64 + nfSlot] = __floats2half2_rn(xv[j].x, xv[j].y);
            g_Pdh [n * 32 + lane]   = __floats2half2_rn(d.x, d.y);
            o.x += bb.x; o.y += bb.y;
            Ob2[n * 32 + lane] = o;
        }
    }
}

// ---------------- hierarchical scan (v13 exact) ----------------

__global__ __launch_bounds__(256) void k_scan_a() {
    int i = blockIdx.x * 256 + threadIdx.x;
    int v = (i < NN) ? g_hist[i] : 0;
    int lane = threadIdx.x & 31;
    int w    = threadIdx.x >> 5;

    int x = v;
#pragma unroll
    for (int o = 1; o < 32; o <<= 1) {
        int t = __shfl_up_sync(0xffffffffu, x, o);
        if (lane >= o) x += t;
    }
    __shared__ int ws[8];
    if (lane == 31) ws[w] = x;
    __syncthreads();
    if (w == 0 && lane < 8) {
        int y = ws[lane];
#pragma unroll
        for (int o = 1; o < 8; o <<= 1) {
            int t = __shfl_up_sync(0xffu, y, o);
            if (lane >= o) y += t;
        }
        ws[lane] = y;
    }
    __syncthreads();
    int incl = x + (w ? ws[w - 1] : 0);
    if (i < NN) g_off[i] = incl - v;               // block-local exclusive
    if (threadIdx.x == 255) g_bsum[blockIdx.x] = incl;
}

__global__ __launch_bounds__(256) void k_scan_b() {
    int t = threadIdx.x;
    int v = (t < NBLK) ? g_bsum[t] : 0;
    int lane = t & 31, w = t >> 5;

    int x = v;
#pragma unroll
    for (int o = 1; o < 32; o <<= 1) {
        int s = __shfl_up_sync(0xffffffffu, x, o);
        if (lane >= o) x += s;
    }
    __shared__ int ws[8];
    if (lane == 31) ws[w] = x;
    __syncthreads();
    if (w == 0 && lane < 8) {
        int y = ws[lane];
#pragma unroll
        for (int o = 1; o < 8; o <<= 1) {
            int s = __shfl_up_sync(0xffu, y, o);
            if (lane >= o) y += s;
        }
        ws[lane] = y;
    }
    __syncthreads();
    int incl = x + (w ? ws[w - 1] : 0);
    if (t < 256) g_bpre[t] = incl - v;             // exclusive block prefix
}

// Scatter src ids into dst-sorted CSR order. Slot = local off + block prefix + rank.
__global__ __launch_bounds__(256) void k_scatter(
    const int* __restrict__ src, const int* __restrict__ dst)
{
    int e = blockIdx.x * blockDim.x + threadIdx.x;
    if (e < NE) {
        int d = __ldg(dst + e);
        int slot = __ldg(&g_off[d]) + __ldg(&g_bpre[d >> 8]) + __ldg(&g_rank[e]);
        g_esrc[slot] = __ldg(src + e);
    }
}

// FUSED edge+node kernel. Half-warp (16 lanes) per dst-node, grid-stride (592 blocks).
// Per-edge 16-lane reduction via group-mask shfl_xor butterfly (proven v13 form).
__global__ __launch_bounds__(256) void k_node(
    const float* __restrict__ ba, const float* __restrict__ wfc,
    const float* __restrict__ Wn, float* __restrict__ out)
{
    __shared__ float sW[4096];  // W_node bottom [64,64]
    for (int i = threadIdx.x; i < 4096; i += blockDim.x)
        sW[i] = Wn[4096 + i];
    __syncthreads();

    const int lane   = threadIdx.x & 31;
    const int gl     = lane & 15;
    const int grp    = lane >> 4;
    const int gbase  = lane & 16;
    const unsigned gmask = 0xFFFFu << gbase;
    const int warp   = (blockIdx.x * blockDim.x + threadIdx.x) >> 5;
    const int nwarps = (gridDim.x * blockDim.x) >> 5;

    float4 b = ((const float4*)ba)[gl];
    float4 w = ((const float4*)wfc)[gl];
    const __half2 w01h = __floats2half2_rn(w.x, w.y);
    const __half2 w23h = __floats2half2_rn(w.z, w.w);
    const __half2 hzero = __floats2half2_rn(0.f, 0.f);

    const uint4*  PsNf = (const uint4*)g_PsNf;
    const uint2*  Pd   = (const uint2*)g_Pdh;
    const float4* sW4  = (const float4*)sW;
    const float4* Ob4  = (const float4*)g_Ob;
    float4*       out4 = (float4*)out;

    for (int v = warp * 2 + grp; v < NN; v += nwarps * 2) {
        int beg = __ldg(&g_off[v]) + __ldg(&g_bpre[v >> 8]);
        int deg = __ldg(&g_hist[v]);
        int end = beg + deg;

        float4 o = Ob4[v * 16 + gl];

        if (deg > 0) {
            uint2 pdu = __ldg(&Pd[v * 16 + gl]);
            float2 pd0 = __half22float2(*(const __half2*)&pdu.x);
            float2 pd1 = __half22float2(*(const __half2*)&pdu.y);
            const __half2 pdb01 = __floats2half2_rn(pd0.x + b.x, pd0.y + b.y);
            const __half2 pdb23 = __floats2half2_rn(pd1.x + b.z, pd1.y + b.w);

            float4 acc = make_float4(0.f, 0.f, 0.f, 0.f);
            float ssum = 0.f;

#pragma unroll 4
            for (int i = beg; i < end; i++) {
                int s = __ldg(&g_esrc[i]);
                uint4 r = __ldg(&PsNf[s * 16 + gl]);

                __half2 h01 = __hmax2(__hadd2(*(const __half2*)&r.x, pdb01), hzero);
                __half2 h23 = __hmax2(__hadd2(*(const __half2*)&r.y, pdb23), hzero);
                __half2 ph  = __hfma2(h23, w23h, __hmul2(h01, w01h));
                float2 pf = __half22float2(ph);
                float p = pf.x + pf.y;

                p += __shfl_xor_sync(gmask, p, 8);
                p += __shfl_xor_sync(gmask, p, 4);
                p += __shfl_xor_sync(gmask, p, 2);
                p += __shfl_xor_sync(gmask, p, 1);

                float lg = fmaxf(p, 0.01f * p);
                float ev = __expf(lg);

                float2 x0 = __half22float2(*(const __half2*)&r.z);
                float2 x1 = __half22float2(*(const __half2*)&r.w);
                acc.x = fmaf(ev, x0.x, acc.x);
                acc.y = fmaf(ev, x0.y, acc.y);
                acc.z = fmaf(ev, x1.x, acc.z);
                acc.w = fmaf(ev, x1.y, acc.w);
                ssum += ev;
            }

            float inv = 1.f / (ssum * (float)deg);
            float a[4] = { acc.x * inv, acc.y * inv, acc.z * inv, acc.w * inv };

#pragma unroll
            for (int k = 0; k < 64; k++) {
                float ak = __shfl_sync(gmask, a[k & 3], gbase + (k >> 2));
                float4 wv = sW4[k * 16 + gl];
                o.x = fmaf(ak, wv.x, o.x);
                o.y = fmaf(ak, wv.y, o.y);
                o.z = fmaf(ak, wv.z, o.z);
                o.w = fmaf(ak, wv.w, o.w);
            }
        }
        out4[v * 16 + gl] = o;
    }
}

// ---------------- launch: fork-join of independent pipelines (v13 exact) ----------------
namespace {
struct SideStream {
    cudaStream_t s;
    cudaEvent_t  fork, join;
    SideStream() {
        cudaStreamCreateWithFlags(&s, cudaStreamNonBlocking);
        cudaEventCreateWithFlags(&fork, cudaEventDisableTiming);
        cudaEventCreateWithFlags(&join, cudaEventDisableTiming);
    }
};
SideStream g_ss;  // constructed at load; no per-call conditionals
}

extern "C" void kernel_launch(void* const* d_in, const int* in_sizes, int n_in,
                              void* d_out, int out_size)
{
    const float* nf   = (const float*)d_in[0];
    const int*   src  = (const int*)d_in[1];
    const int*   dst  = (const int*)d_in[2];
    const float* Wa   = (const float*)d_in[3];
    const float* ba   = (const float*)d_in[4];
    const float* wfc  = (const float*)d_in[5];
    const float* Wn   = (const float*)d_in[6];
    const float* bn   = (const float*)d_in[7];
    float*       out  = (float*)d_out;

    (void)in_sizes; (void)n_in; (void)out_size;

    // fork: side stream runs the graph-structure pipeline (ints only)
    cudaEventRecord(g_ss.fork, 0);
    cudaStreamWaitEvent(g_ss.s, g_ss.fork, 0);

    k_zero_hist<<<(NN + 255) / 256, 256, 0, g_ss.s>>>();
    k_hist<<<(NE / 8 + 255) / 256, 256, 0, g_ss.s>>>(dst);
    k_scan_a<<<NBLK, 256, 0, g_ss.s>>>();
    k_scan_b<<<1, 256, 0, g_ss.s>>>();
    k_scatter<<<(NE + 255) / 256, 256, 0, g_ss.s>>>(src, dst);
    cudaEventRecord(g_ss.join, g_ss.s);

    // main stream: feature projections (floats only), concurrent with above
    k_proj<<<592, 256>>>(nf, Wa, Wn, bn);

    // join, then fused edge+node kernel
    cudaStreamWaitEvent(0, g_ss.join, 0);
    k_node<<<592, 256>>>(ba, wfc, Wn, out);
}